// round 15
// baseline (speedup 1.0000x reference)
#include <cuda_runtime.h>
#include <cuda_fp16.h>
#include <cstdint>

#define EPSB 1e-5f

static constexpr int B_   = 2;
static constexpr int N_   = 250000;
static constexpr int P_   = B_ * N_;            // 500000
static constexpr int G_   = 64;
static constexpr int NS_  = B_ * G_ * G_ * G_;  // 524288
static constexpr int OUT_ = 64;
static constexpr int TIL  = 256;                // points per CTA
static constexpr int NT_CTA = (P_ + TIL - 1) / TIL;  // 1954
static constexpr int THR  = 512;                // 16 warps

// ---------------- device scratch (no allocation) ---------------------------
__device__ float g_W0f[3 * 64];
__device__ float g_b0f[64];
__device__ float g_b1f[128];
__device__ float g_b2f[256];
// folded, transposed [n][k], single fp16, SW128 pre-swizzled, sliced
__device__ __align__(16) unsigned char g_Wh1[16384];   // [128n][64k]
__device__ __align__(16) unsigned char g_Wh2[65536];   // 4 x 16KB slices (g*2+kc)
__device__ __align__(16) unsigned char g_Wh3[32768];   // 4 x 8KB slices (kc): [64n][64k]

__host__ __device__ __forceinline__ uint32_t sw128(uint32_t o) {
    return o ^ ((o >> 3) & 0x70u);
}

// ---------------- helpers ----------------------------------------------------
__device__ __forceinline__ uint32_t smem_u32(const void* p) {
    uint32_t a;
    asm("{ .reg .u64 t; cvta.to.shared.u64 t, %1; cvt.u32.u64 %0, t; }"
        : "=r"(a) : "l"(p));
    return a;
}
__device__ __forceinline__ void ldsm_x4(uint32_t& r0, uint32_t& r1,
                                        uint32_t& r2, uint32_t& r3, uint32_t addr) {
    asm volatile("ldmatrix.sync.aligned.m8n8.x4.shared.b16 {%0,%1,%2,%3}, [%4];"
                 : "=r"(r0), "=r"(r1), "=r"(r2), "=r"(r3) : "r"(addr));
}
__device__ __forceinline__ void mma_f16(float (&c)[4], const uint32_t (&a)[4],
                                        const uint32_t (&b)[2]) {
    asm volatile("mma.sync.aligned.m16n8k16.row.col.f32.f16.f16.f32 "
                 "{%0,%1,%2,%3}, {%4,%5,%6,%7}, {%8,%9}, {%0,%1,%2,%3};"
                 : "+f"(c[0]), "+f"(c[1]), "+f"(c[2]), "+f"(c[3])
                 : "r"(a[0]), "r"(a[1]), "r"(a[2]), "r"(a[3]), "r"(b[0]), "r"(b[1]));
}
// pack two f32 -> f16x2 word: v0 -> bits[15:0], v1 -> bits[31:16]
__device__ __forceinline__ uint32_t pack2h(float v0, float v1) {
    uint32_t r;
    asm("cvt.rn.f16x2.f32 %0, %1, %2;" : "=r"(r) : "f"(v1), "f"(v0));
    return r;
}

// order-preserving float -> uint encode (branchless scatter-max)
__device__ __forceinline__ unsigned encf(float f) {
    unsigned u = __float_as_uint(f);
    return (u & 0x80000000u) ? ~u : (u | 0x80000000u);
}
__device__ __forceinline__ unsigned decf(unsigned u) {
    if (u == 0u) return 0u;
    return (u & 0x80000000u) ? (u & 0x7FFFFFFFu) : ~u;
}

// cp.async staging (512 threads)
__device__ __forceinline__ void stage_async(uint32_t sdst, const unsigned char* g,
                                            int bytes, int tid) {
    for (int i = tid * 16; i < bytes; i += THR * 16)
        asm volatile("cp.async.cg.shared.global [%0], [%1], 16;"
                     :: "r"(sdst + (uint32_t)i), "l"(g + i));
}
#define CP_COMMIT() asm volatile("cp.async.commit_group;" ::: "memory")
#define CP_WAIT0()  asm volatile("cp.async.wait_group 0;" ::: "memory")

// ---------------- merged init + BN-fold kernel (2 uint4 / thread) ------------
__global__ void init_fold_kernel(
    uint4* __restrict__ o, int n4,
    const float* __restrict__ bn0g, const float* __restrict__ bn0b,
    const float* __restrict__ bn0m, const float* __restrict__ bn0v,
    const float* __restrict__ bn1g, const float* __restrict__ bn1b,
    const float* __restrict__ bn1m, const float* __restrict__ bn1v,
    const float* __restrict__ bn2g, const float* __restrict__ bn2b,
    const float* __restrict__ bn2m, const float* __restrict__ bn2v,
    const float* __restrict__ bn3g, const float* __restrict__ bn3b,
    const float* __restrict__ bn3m, const float* __restrict__ bn3v,
    const float* __restrict__ W0, const float* __restrict__ b0,
    const float* __restrict__ W1, const float* __restrict__ b1,
    const float* __restrict__ W2, const float* __restrict__ b2,
    const float* __restrict__ W3)
{
    const int gi = blockIdx.x * 256 + threadIdx.x;
    const uint4 z = make_uint4(0u, 0u, 0u, 0u);
    int i0 = gi * 2;
    if (i0 < n4)     o[i0]     = z;
    if (i0 + 1 < n4) o[i0 + 1] = z;

    if (blockIdx.x < 64) {
        const int gt = gi;
        const int GS = 64 * 256;

        for (int idx = gt; idx < 3 * 64; idx += GS) {
            int i = idx / 64, j = idx % 64;
            float s0 = bn0g[i] * rsqrtf(bn0v[i] + EPSB);
            float s1 = bn1g[j] * rsqrtf(bn1v[j] + EPSB);
            g_W0f[idx] = s0 * W0[idx] * s1;
        }
        for (int j = gt; j < 64; j += GS) {
            float s1 = bn1g[j] * rsqrtf(bn1v[j] + EPSB);
            float sum = 0.f;
            for (int i = 0; i < 3; i++) {
                float s0 = bn0g[i] * rsqrtf(bn0v[i] + EPSB);
                float c0 = bn0b[i] - bn0m[i] * s0;
                sum += c0 * W0[i * 64 + j];
            }
            g_b0f[j] = s1 * (sum + b0[j] - bn1m[j]) + bn1b[j];
        }

        // L1: [128n][64k] fp16, sw128
        for (int idx = gt; idx < 128 * 64; idx += GS) {
            int n = idx >> 6, k = idx & 63;
            float s2 = bn2g[n] * rsqrtf(bn2v[n] + EPSB);
            float w = W1[k * 128 + n] * s2;
            uint32_t off = sw128((uint32_t)(n * 128 + k * 2));
            *(__half*)(g_Wh1 + off) = __float2half_rn(w);
        }
        for (int n = gt; n < 128; n += GS) {
            float s2 = bn2g[n] * rsqrtf(bn2v[n] + EPSB);
            g_b1f[n] = s2 * (b1[n] - bn2m[n]) + bn2b[n];
        }

        // L2: slice (g*2+kc) of 16KB each
        for (int idx = gt; idx < 256 * 128; idx += GS) {
            int n = idx >> 7, k = idx & 127;
            float s3 = bn3g[n] * rsqrtf(bn3v[n] + EPSB);
            float w = W2[k * 256 + n] * s3;
            int g = n >> 7, kc = k >> 6, nl = n & 127, kl = k & 63;
            uint32_t base = (uint32_t)(g * 2 + kc) * 16384u;
            uint32_t off  = sw128((uint32_t)(nl * 128 + kl * 2));
            *(__half*)(g_Wh2 + base + off) = __float2half_rn(w);
        }
        for (int n = gt; n < 256; n += GS) {
            float s3 = bn3g[n] * rsqrtf(bn3v[n] + EPSB);
            g_b2f[n] = s3 * (b2[n] - bn3m[n]) + bn3b[n];
        }

        // L3: slice (kc) of 8KB each: [64n][64k]
        for (int idx = gt; idx < 64 * 256; idx += GS) {
            int n = idx / 256, k = idx % 256;
            float w = W3[k * 64 + n];
            int kc = k >> 6, kl = k & 63;
            uint32_t base = (uint32_t)kc * 8192u;
            uint32_t off  = sw128((uint32_t)(n * 128 + kl * 2));
            *(__half*)(g_Wh3 + base + off) = __float2half_rn(w);
        }
    }
}

// ---------------- decode (2 uint4 / thread) ----------------------------------
__global__ void decode_kernel(uint4* __restrict__ o, int n4) {
    int gi = blockIdx.x * 256 + threadIdx.x;
    int i0 = gi * 2;
    #pragma unroll
    for (int s = 0; s < 2; s++) {
        int i = i0 + s;
        if (i < n4) {
            uint4 v = o[i];
            v.x = decf(v.x); v.y = decf(v.y); v.z = decf(v.z); v.w = decf(v.w);
            o[i] = v;
        }
    }
}

// ---------------- SMEM layout ------------------------------------------------
// 6 act slots (32KB each: [256 rows][128B], single fp16), 2 weight bufs, misc
__host__ __device__ constexpr uint32_t SLOT(int i) { return (uint32_t)i * 32768u; }
static constexpr uint32_t WBUF  = 196608;                // WB0 @ +0, WB1 @ +16384
static constexpr uint32_t MISC  = 229376;
static constexpr uint32_t BIAS1 = MISC;                  // 128 f32
static constexpr uint32_t BIAS2 = MISC + 512;            // 256 f32
static constexpr uint32_t BIAS3 = MISC + 1536;           // 64 f32
static constexpr uint32_t SEGO  = MISC + 1792;           // 256 int
static constexpr uint32_t SMEM_TOTAL = SEGO + 1024;

// ---------------- warp GEMM over one 64-K chunk (m32 = 2 m-tiles) ------------
template<int NT>
__device__ __forceinline__ void mma_kchunk1(
    float (&acc)[2][NT][4],
    uint32_t aW,                  // act slot base + wm*32*128
    uint32_t bW,                  // weight slice base + wn*(NT*8)*128
    int lane)
{
    const int rA  = (lane & 7) + ((lane >> 3) & 1) * 8;
    const int kA8 = ((lane >> 4) & 1) * 8;
    const uint32_t xorA = (uint32_t)((rA & 7) << 4);
    const int rB  = (lane & 7) + ((lane >> 4) & 1) * 8;
    const int kB8 = ((lane >> 3) & 1) * 8;
    const uint32_t xorB = (uint32_t)((lane & 7) << 4);

    #pragma unroll
    for (int ks = 0; ks < 4; ks++) {
        const int k0 = ks * 16;
        uint32_t ah[2][4];
        #pragma unroll
        for (int mt = 0; mt < 2; mt++) {
            uint32_t off = (uint32_t)((mt * 16 + rA) * 128)
                         + (((uint32_t)(k0 + kA8) << 1) ^ xorA);
            ldsm_x4(ah[mt][0], ah[mt][1], ah[mt][2], ah[mt][3], aW + off);
        }
        uint32_t bw[NT][2];
        #pragma unroll
        for (int q = 0; q < NT / 2; q++) {
            uint32_t off = (uint32_t)((q * 16 + rB) * 128)
                         + (((uint32_t)(k0 + kB8) << 1) ^ xorB);
            ldsm_x4(bw[2*q][0], bw[2*q][1], bw[2*q+1][0], bw[2*q+1][1], bW + off);
        }
        #pragma unroll
        for (int mt = 0; mt < 2; mt++)
            #pragma unroll
            for (int nt = 0; nt < NT; nt++)
                mma_f16(acc[mt][nt], ah[mt], bw[nt]);
    }
}

// hidden-layer epilogue: acc -> bias -> relu -> fp16 -> act slot (64 cols)
template<int NT>
__device__ __forceinline__ void epi_hidden(
    float (&acc)[2][NT][4], unsigned char* smem, uint32_t outOff,
    const float* sBias, int colBase, int wm, int lane)
{
    const int r0 = lane >> 2;
    #pragma unroll
    for (int mt = 0; mt < 2; mt++) {
        int row1 = wm * 32 + mt * 16 + r0;
        int row2 = row1 + 8;
        #pragma unroll
        for (int nt = 0; nt < NT; nt++) {
            int kl = nt * 8 + (lane & 3) * 2;
            float bi0 = sBias[colBase + kl], bi1 = sBias[colBase + kl + 1];
            {
                float v0 = fmaxf(acc[mt][nt][0] + bi0, 0.f);
                float v1 = fmaxf(acc[mt][nt][1] + bi1, 0.f);
                uint32_t off = (uint32_t)(row1 * 128)
                             + (((uint32_t)kl << 1) ^ ((uint32_t)(row1 & 7) << 4));
                *(uint32_t*)(smem + outOff + off) = pack2h(v0, v1);
            }
            {
                float v0 = fmaxf(acc[mt][nt][2] + bi0, 0.f);
                float v1 = fmaxf(acc[mt][nt][3] + bi1, 0.f);
                uint32_t off = (uint32_t)(row2 * 128)
                             + (((uint32_t)kl << 1) ^ ((uint32_t)(row2 & 7) << 4));
                *(uint32_t*)(smem + outOff + off) = pack2h(v0, v1);
            }
        }
    }
}

// ---------------- fused MLP + scatter (R7 structure, merged L3 staging) ------
__global__ void __launch_bounds__(THR, 1) mlp_kernel(
    const float* __restrict__ pt_fea, const int* __restrict__ pt_ind,
    const float* __restrict__ b3, unsigned* __restrict__ out)
{
    extern __shared__ __align__(1024) unsigned char smem[];
    float* sB1 = (float*)(smem + BIAS1);
    float* sB2 = (float*)(smem + BIAS2);
    float* sB3 = (float*)(smem + BIAS3);
    int*   sSeg = (int*)(smem + SEGO);
    const uint32_t sb = smem_u32(smem);
    const uint32_t WB0 = sb + WBUF, WB1 = sb + WBUF + 16384;

    const int tid = threadIdx.x, wid = tid >> 5, lane = tid & 31;
    const int wm = wid & 7, wn = wid >> 3;   // 8 m-groups (32 rows) x 2 n-groups
    const int blk = blockIdx.x;
    const uint32_t aWm = (uint32_t)(wm * 32 * 128);

    // ---- prologue: kick S0, stage biases/segs, L0 compute ----
    stage_async(WB0, g_Wh1, 16384, tid); CP_COMMIT();

    if (tid < 256) {
        int gp = blk * TIL + tid;
        int seg = -1;
        if (gp < P_) {
            int ix = pt_ind[3 * gp], iy = pt_ind[3 * gp + 1], iz = pt_ind[3 * gp + 2];
            int bb = (gp >= N_) ? 1 : 0;
            seg = ((bb * G_ + iz) * G_ + iy) * G_ + ix;
        }
        sSeg[tid] = seg;
    }
    if (tid < 128) sB1[tid] = g_b1f[tid];
    if (tid < 256) sB2[tid] = g_b2f[tid];
    if (tid < 64)  sB3[tid] = b3[tid];

    // L0: 3 -> 64 scalar fp32, fp16 into slot 0 (256 points, 2 threads/pt)
    {
        int p = tid >> 1, j0 = (tid & 1) * 32;
        int gp = blk * TIL + p;
        float x0 = 0.f, x1 = 0.f, x2 = 0.f;
        if (gp < P_) { x0 = pt_fea[gp*3]; x1 = pt_fea[gp*3+1]; x2 = pt_fea[gp*3+2]; }
        #pragma unroll
        for (int j = 0; j < 32; j += 2) {
            int k = j0 + j;
            float v0 = g_b0f[k]   + x0*g_W0f[k]   + x1*g_W0f[64+k]   + x2*g_W0f[128+k];
            float v1 = g_b0f[k+1] + x0*g_W0f[k+1] + x1*g_W0f[64+k+1] + x2*g_W0f[128+k+1];
            v0 = fmaxf(v0, 0.f); v1 = fmaxf(v1, 0.f);
            uint32_t off = sw128((uint32_t)(p * 128 + k * 2));
            *(uint32_t*)(smem + SLOT(0) + off) = pack2h(v0, v1);
        }
    }
    CP_WAIT0();
    __syncthreads();

    // ---- p0: L1 (64->128), in slot0, out slots 1,2; prefetch S1 ----
    stage_async(WB1, g_Wh2, 16384, tid); CP_COMMIT();
    {
        float acc[2][8][4];
        #pragma unroll
        for (int a = 0; a < 2; a++)
            #pragma unroll
            for (int b = 0; b < 8; b++)
                #pragma unroll
                for (int c = 0; c < 4; c++) acc[a][b][c] = 0.f;
        uint32_t bOff = (uint32_t)(wn * 64 * 128);
        mma_kchunk1<8>(acc, sb + SLOT(0) + aWm, WB0 + bOff, lane);
        epi_hidden<8>(acc, smem, SLOT(1 + wn), sB1, wn * 64, wm, lane);
    }
    CP_WAIT0(); __syncthreads();

    // ---- L2 (128->256): g0 over p1,p2 ; g1 over p3,p4 ----
    const int outSlot[4] = {3, 4, 5, 0};
    {
        float acc[2][8][4];
        uint32_t bOff = (uint32_t)(wn * 64 * 128);

        // p1: g0 kc0 on WB1(S1); prefetch S2 -> WB0
        stage_async(WB0, g_Wh2 + 16384, 16384, tid); CP_COMMIT();
        #pragma unroll
        for (int a = 0; a < 2; a++)
            #pragma unroll
            for (int b = 0; b < 8; b++)
                #pragma unroll
                for (int c = 0; c < 4; c++) acc[a][b][c] = 0.f;
        mma_kchunk1<8>(acc, sb + SLOT(1) + aWm, WB1 + bOff, lane);
        CP_WAIT0(); __syncthreads();

        // p2: g0 kc1 on WB0(S2); prefetch S3 -> WB1
        stage_async(WB1, g_Wh2 + 32768, 16384, tid); CP_COMMIT();
        mma_kchunk1<8>(acc, sb + SLOT(2) + aWm, WB0 + bOff, lane);
        epi_hidden<8>(acc, smem, SLOT(outSlot[wn]), sB2, wn * 64, wm, lane);
        CP_WAIT0(); __syncthreads();

        // p3: g1 kc0 on WB1(S3); prefetch S4 -> WB0
        stage_async(WB0, g_Wh2 + 49152, 16384, tid); CP_COMMIT();
        #pragma unroll
        for (int a = 0; a < 2; a++)
            #pragma unroll
            for (int b = 0; b < 8; b++)
                #pragma unroll
                for (int c = 0; c < 4; c++) acc[a][b][c] = 0.f;
        mma_kchunk1<8>(acc, sb + SLOT(1) + aWm, WB1 + bOff, lane);
        CP_WAIT0(); __syncthreads();

        // p4: g1 kc1 on WB0(S4); prefetch L3 kc0+kc1 (16KB) -> WB1
        stage_async(WB1, g_Wh3, 16384, tid); CP_COMMIT();
        mma_kchunk1<8>(acc, sb + SLOT(2) + aWm, WB0 + bOff, lane);
        epi_hidden<8>(acc, smem, SLOT(outSlot[2 + wn]), sB2, 128 + wn * 64, wm, lane);
        CP_WAIT0(); __syncthreads();
    }

    // ---- L3 (256->64) over p5,p6 (merged kc pairs), then scatter ----
    {
        float acc[2][4][4];
        #pragma unroll
        for (int a = 0; a < 2; a++)
            #pragma unroll
            for (int b = 0; b < 4; b++)
                #pragma unroll
                for (int c = 0; c < 4; c++) acc[a][b][c] = 0.f;
        uint32_t bOff = (uint32_t)(wn * 32 * 128);

        // p5: kc0 (slot3, WB1+0) + kc1 (slot4, WB1+8192); prefetch kc2+kc3 -> WB0
        stage_async(WB0, g_Wh3 + 16384, 16384, tid); CP_COMMIT();
        mma_kchunk1<4>(acc, sb + SLOT(3) + aWm, WB1 + bOff, lane);
        mma_kchunk1<4>(acc, sb + SLOT(4) + aWm, WB1 + 8192 + bOff, lane);
        CP_WAIT0(); __syncthreads();

        // p6: kc2 (slot5, WB0+0) + kc3 (slot0, WB0+8192)
        mma_kchunk1<4>(acc, sb + SLOT(5) + aWm, WB0 + bOff, lane);
        mma_kchunk1<4>(acc, sb + SLOT(0) + aWm, WB0 + 8192 + bOff, lane);

        // scatter-max (branchless encode)
        const int r0 = lane >> 2;
        #pragma unroll
        for (int mt = 0; mt < 2; mt++) {
            int row1 = wm * 32 + mt * 16 + r0;
            int row2 = row1 + 8;
            int seg1 = sSeg[row1], seg2 = sSeg[row2];
            #pragma unroll
            for (int nt = 0; nt < 4; nt++) {
                int col = wn * 32 + nt * 8 + (lane & 3) * 2;
                float bi0 = sB3[col], bi1 = sB3[col + 1];
                if (seg1 >= 0) {
                    unsigned b0a = (unsigned)seg1 * 64u + (unsigned)col;
                    atomicMax(out + b0a,     encf(acc[mt][nt][0] + bi0));
                    atomicMax(out + b0a + 1, encf(acc[mt][nt][1] + bi1));
                }
                if (seg2 >= 0) {
                    unsigned b0a = (unsigned)seg2 * 64u + (unsigned)col;
                    atomicMax(out + b0a,     encf(acc[mt][nt][2] + bi0));
                    atomicMax(out + b0a + 1, encf(acc[mt][nt][3] + bi1));
                }
            }
        }
    }
}

// ---------------- launcher ---------------------------------------------------
extern "C" void kernel_launch(void* const* d_in, const int* in_sizes, int n_in,
                              void* d_out, int out_size)
{
    const float* pt_fea = (const float*)d_in[0];
    const int*   pt_ind = (const int*)  d_in[1];
    const float *bn0g = (const float*)d_in[2],  *bn0b = (const float*)d_in[3],
                *bn0m = (const float*)d_in[4],  *bn0v = (const float*)d_in[5];
    const float *bn1g = (const float*)d_in[6],  *bn1b = (const float*)d_in[7],
                *bn1m = (const float*)d_in[8],  *bn1v = (const float*)d_in[9];
    const float *bn2g = (const float*)d_in[10], *bn2b = (const float*)d_in[11],
                *bn2m = (const float*)d_in[12], *bn2v = (const float*)d_in[13];
    const float *bn3g = (const float*)d_in[14], *bn3b = (const float*)d_in[15],
                *bn3m = (const float*)d_in[16], *bn3v = (const float*)d_in[17];
    const float *W0 = (const float*)d_in[18], *b0 = (const float*)d_in[19];
    const float *W1 = (const float*)d_in[20], *b1 = (const float*)d_in[21];
    const float *W2 = (const float*)d_in[22], *b2 = (const float*)d_in[23];
    const float *W3 = (const float*)d_in[24], *b3 = (const float*)d_in[25];

    cudaFuncSetAttribute(mlp_kernel, cudaFuncAttributeMaxDynamicSharedMemorySize,
                         SMEM_TOTAL);

    const int n4 = NS_ * OUT_ / 4;
    const int nblk2 = (n4 / 2 + 255) / 256;    // 2 uint4 per thread
    init_fold_kernel<<<nblk2, 256>>>(
        (uint4*)d_out, n4,
        bn0g, bn0b, bn0m, bn0v, bn1g, bn1b, bn1m, bn1v,
        bn2g, bn2b, bn2m, bn2v, bn3g, bn3b, bn3m, bn3v,
        W0, b0, W1, b1, W2, b2, W3);

    mlp_kernel<<<NT_CTA, THR, SMEM_TOTAL>>>(pt_fea, pt_ind, b3, (unsigned*)d_out);

    decode_kernel<<<nblk2, 256>>>((uint4*)d_out, n4);
}

// round 16
// speedup vs baseline: 1.0399x; 1.0399x over previous
#include <cuda_runtime.h>
#include <cuda_fp16.h>
#include <cstdint>

#define EPSB 1e-5f

static constexpr int B_   = 2;
static constexpr int N_   = 250000;
static constexpr int P_   = B_ * N_;            // 500000
static constexpr int G_   = 64;
static constexpr int NS_  = B_ * G_ * G_ * G_;  // 524288
static constexpr int OUT_ = 64;
static constexpr int TIL  = 256;                // points per CTA
static constexpr int NT_CTA = (P_ + TIL - 1) / TIL;  // 1954
static constexpr int THR  = 512;                // 16 warps

// ---------------- device scratch (no allocation) ---------------------------
__device__ float g_W0f[3 * 64];
__device__ float g_b0f[64];
__device__ float g_b1f[128];
__device__ float g_b2f[256];
// folded, transposed [n][k], single fp16, SW128 pre-swizzled, sliced
__device__ __align__(16) unsigned char g_Wh1[16384];   // [128n][64k]
__device__ __align__(16) unsigned char g_Wh2[65536];   // 4 x 16KB slices (g*2+kc)
__device__ __align__(16) unsigned char g_Wh3[32768];   // 4 x 8KB slices (kc): [64n][64k]

__host__ __device__ __forceinline__ uint32_t sw128(uint32_t o) {
    return o ^ ((o >> 3) & 0x70u);
}

// ---------------- helpers ----------------------------------------------------
__device__ __forceinline__ uint32_t smem_u32(const void* p) {
    uint32_t a;
    asm("{ .reg .u64 t; cvta.to.shared.u64 t, %1; cvt.u32.u64 %0, t; }"
        : "=r"(a) : "l"(p));
    return a;
}
__device__ __forceinline__ void ldsm_x4(uint32_t& r0, uint32_t& r1,
                                        uint32_t& r2, uint32_t& r3, uint32_t addr) {
    asm volatile("ldmatrix.sync.aligned.m8n8.x4.shared.b16 {%0,%1,%2,%3}, [%4];"
                 : "=r"(r0), "=r"(r1), "=r"(r2), "=r"(r3) : "r"(addr));
}
__device__ __forceinline__ void mma_f16(float (&c)[4], const uint32_t (&a)[4],
                                        const uint32_t (&b)[2]) {
    asm volatile("mma.sync.aligned.m16n8k16.row.col.f32.f16.f16.f32 "
                 "{%0,%1,%2,%3}, {%4,%5,%6,%7}, {%8,%9}, {%0,%1,%2,%3};"
                 : "+f"(c[0]), "+f"(c[1]), "+f"(c[2]), "+f"(c[3])
                 : "r"(a[0]), "r"(a[1]), "r"(a[2]), "r"(a[3]), "r"(b[0]), "r"(b[1]));
}
// pack two f32 -> f16x2 word: v0 -> bits[15:0], v1 -> bits[31:16]
__device__ __forceinline__ uint32_t pack2h(float v0, float v1) {
    uint32_t r;
    asm("cvt.rn.f16x2.f32 %0, %1, %2;" : "=r"(r) : "f"(v1), "f"(v0));
    return r;
}

// order-preserving float -> uint encode (branchless scatter-max)
__device__ __forceinline__ unsigned encf(float f) {
    unsigned u = __float_as_uint(f);
    return (u & 0x80000000u) ? ~u : (u | 0x80000000u);
}
__device__ __forceinline__ unsigned decf(unsigned u) {
    if (u == 0u) return 0u;
    return (u & 0x80000000u) ? (u & 0x7FFFFFFFu) : ~u;
}

// cp.async staging (512 threads)
__device__ __forceinline__ void stage_async(uint32_t sdst, const unsigned char* g,
                                            int bytes, int tid) {
    for (int i = tid * 16; i < bytes; i += THR * 16)
        asm volatile("cp.async.cg.shared.global [%0], [%1], 16;"
                     :: "r"(sdst + (uint32_t)i), "l"(g + i));
}
#define CP_COMMIT() asm volatile("cp.async.commit_group;" ::: "memory")
#define CP_WAIT0()  asm volatile("cp.async.wait_group 0;" ::: "memory")

// ---------------- merged init + BN-fold kernel ------------------------------
// Blocks 0..63 additionally perform the fold work; it hides completely under
// the DRAM-bound 134MB zero-init performed by all 32768 blocks.
__global__ void init_fold_kernel(
    uint4* __restrict__ o, int n4,
    const float* __restrict__ bn0g, const float* __restrict__ bn0b,
    const float* __restrict__ bn0m, const float* __restrict__ bn0v,
    const float* __restrict__ bn1g, const float* __restrict__ bn1b,
    const float* __restrict__ bn1m, const float* __restrict__ bn1v,
    const float* __restrict__ bn2g, const float* __restrict__ bn2b,
    const float* __restrict__ bn2m, const float* __restrict__ bn2v,
    const float* __restrict__ bn3g, const float* __restrict__ bn3b,
    const float* __restrict__ bn3m, const float* __restrict__ bn3v,
    const float* __restrict__ W0, const float* __restrict__ b0,
    const float* __restrict__ W1, const float* __restrict__ b1,
    const float* __restrict__ W2, const float* __restrict__ b2,
    const float* __restrict__ W3)
{
    const int gi = blockIdx.x * 256 + threadIdx.x;
    if (gi < n4) o[gi] = make_uint4(0u, 0u, 0u, 0u);

    if (blockIdx.x < 64) {
        const int gt = gi;
        const int GS = 64 * 256;

        for (int idx = gt; idx < 3 * 64; idx += GS) {
            int i = idx / 64, j = idx % 64;
            float s0 = bn0g[i] * rsqrtf(bn0v[i] + EPSB);
            float s1 = bn1g[j] * rsqrtf(bn1v[j] + EPSB);
            g_W0f[idx] = s0 * W0[idx] * s1;
        }
        for (int j = gt; j < 64; j += GS) {
            float s1 = bn1g[j] * rsqrtf(bn1v[j] + EPSB);
            float sum = 0.f;
            for (int i = 0; i < 3; i++) {
                float s0 = bn0g[i] * rsqrtf(bn0v[i] + EPSB);
                float c0 = bn0b[i] - bn0m[i] * s0;
                sum += c0 * W0[i * 64 + j];
            }
            g_b0f[j] = s1 * (sum + b0[j] - bn1m[j]) + bn1b[j];
        }

        // L1: [128n][64k] fp16, sw128
        for (int idx = gt; idx < 128 * 64; idx += GS) {
            int n = idx >> 6, k = idx & 63;
            float s2 = bn2g[n] * rsqrtf(bn2v[n] + EPSB);
            float w = W1[k * 128 + n] * s2;
            uint32_t off = sw128((uint32_t)(n * 128 + k * 2));
            *(__half*)(g_Wh1 + off) = __float2half_rn(w);
        }
        for (int n = gt; n < 128; n += GS) {
            float s2 = bn2g[n] * rsqrtf(bn2v[n] + EPSB);
            g_b1f[n] = s2 * (b1[n] - bn2m[n]) + bn2b[n];
        }

        // L2: slice (g*2+kc) of 16KB each
        for (int idx = gt; idx < 256 * 128; idx += GS) {
            int n = idx >> 7, k = idx & 127;
            float s3 = bn3g[n] * rsqrtf(bn3v[n] + EPSB);
            float w = W2[k * 256 + n] * s3;
            int g = n >> 7, kc = k >> 6, nl = n & 127, kl = k & 63;
            uint32_t base = (uint32_t)(g * 2 + kc) * 16384u;
            uint32_t off  = sw128((uint32_t)(nl * 128 + kl * 2));
            *(__half*)(g_Wh2 + base + off) = __float2half_rn(w);
        }
        for (int n = gt; n < 256; n += GS) {
            float s3 = bn3g[n] * rsqrtf(bn3v[n] + EPSB);
            g_b2f[n] = s3 * (b2[n] - bn3m[n]) + bn3b[n];
        }

        // L3: slice (kc) of 8KB each: [64n][64k]
        for (int idx = gt; idx < 64 * 256; idx += GS) {
            int n = idx / 256, k = idx % 256;
            float w = W3[k * 64 + n];
            int kc = k >> 6, kl = k & 63;
            uint32_t base = (uint32_t)kc * 8192u;
            uint32_t off  = sw128((uint32_t)(n * 128 + kl * 2));
            *(__half*)(g_Wh3 + base + off) = __float2half_rn(w);
        }
    }
}

// ---------------- decode (plain streaming) -----------------------------------
__global__ void decode_kernel(uint4* __restrict__ o, int n4) {
    int i = blockIdx.x * 256 + threadIdx.x;
    if (i < n4) {
        uint4 v = o[i];
        v.x = decf(v.x); v.y = decf(v.y); v.z = decf(v.z); v.w = decf(v.w);
        o[i] = v;
    }
}

// ---------------- SMEM layout ------------------------------------------------
// 6 act slots (32KB each: [256 rows][128B], single fp16), 2 weight bufs, misc
__host__ __device__ constexpr uint32_t SLOT(int i) { return (uint32_t)i * 32768u; }
static constexpr uint32_t WBUF  = 196608;                // WB0 @ +0, WB1 @ +16384
static constexpr uint32_t MISC  = 229376;
static constexpr uint32_t BIAS1 = MISC;                  // 128 f32
static constexpr uint32_t BIAS2 = MISC + 512;            // 256 f32
static constexpr uint32_t BIAS3 = MISC + 1536;           // 64 f32
static constexpr uint32_t SEGO  = MISC + 1792;           // 256 int
static constexpr uint32_t SMEM_TOTAL = SEGO + 1024;

// ---------------- warp GEMM over one 64-K chunk (m32 = 2 m-tiles) ------------
template<int NT>
__device__ __forceinline__ void mma_kchunk1(
    float (&acc)[2][NT][4],
    uint32_t aW,                  // act slot base + wm*32*128
    uint32_t bW,                  // weight slice base + wn*(NT*8)*128
    int lane)
{
    const int rA  = (lane & 7) + ((lane >> 3) & 1) * 8;
    const int kA8 = ((lane >> 4) & 1) * 8;
    const uint32_t xorA = (uint32_t)((rA & 7) << 4);
    const int rB  = (lane & 7) + ((lane >> 4) & 1) * 8;
    const int kB8 = ((lane >> 3) & 1) * 8;
    const uint32_t xorB = (uint32_t)((lane & 7) << 4);

    #pragma unroll
    for (int ks = 0; ks < 4; ks++) {
        const int k0 = ks * 16;
        uint32_t ah[2][4];
        #pragma unroll
        for (int mt = 0; mt < 2; mt++) {
            uint32_t off = (uint32_t)((mt * 16 + rA) * 128)
                         + (((uint32_t)(k0 + kA8) << 1) ^ xorA);
            ldsm_x4(ah[mt][0], ah[mt][1], ah[mt][2], ah[mt][3], aW + off);
        }
        uint32_t bw[NT][2];
        #pragma unroll
        for (int q = 0; q < NT / 2; q++) {
            uint32_t off = (uint32_t)((q * 16 + rB) * 128)
                         + (((uint32_t)(k0 + kB8) << 1) ^ xorB);
            ldsm_x4(bw[2*q][0], bw[2*q][1], bw[2*q+1][0], bw[2*q+1][1], bW + off);
        }
        #pragma unroll
        for (int mt = 0; mt < 2; mt++)
            #pragma unroll
            for (int nt = 0; nt < NT; nt++)
                mma_f16(acc[mt][nt], ah[mt], bw[nt]);
    }
}

// hidden-layer epilogue: acc -> bias -> relu -> fp16 -> act slot (64 cols)
template<int NT>
__device__ __forceinline__ void epi_hidden(
    float (&acc)[2][NT][4], unsigned char* smem, uint32_t outOff,
    const float* sBias, int colBase, int wm, int lane)
{
    const int r0 = lane >> 2;
    #pragma unroll
    for (int mt = 0; mt < 2; mt++) {
        int row1 = wm * 32 + mt * 16 + r0;
        int row2 = row1 + 8;
        #pragma unroll
        for (int nt = 0; nt < NT; nt++) {
            int kl = nt * 8 + (lane & 3) * 2;
            float bi0 = sBias[colBase + kl], bi1 = sBias[colBase + kl + 1];
            {
                float v0 = fmaxf(acc[mt][nt][0] + bi0, 0.f);
                float v1 = fmaxf(acc[mt][nt][1] + bi1, 0.f);
                uint32_t off = (uint32_t)(row1 * 128)
                             + (((uint32_t)kl << 1) ^ ((uint32_t)(row1 & 7) << 4));
                *(uint32_t*)(smem + outOff + off) = pack2h(v0, v1);
            }
            {
                float v0 = fmaxf(acc[mt][nt][2] + bi0, 0.f);
                float v1 = fmaxf(acc[mt][nt][3] + bi1, 0.f);
                uint32_t off = (uint32_t)(row2 * 128)
                             + (((uint32_t)kl << 1) ^ ((uint32_t)(row2 & 7) << 4));
                *(uint32_t*)(smem + outOff + off) = pack2h(v0, v1);
            }
        }
    }
}

// ---------------- fused MLP + scatter (R7 structure) -------------------------
__global__ void __launch_bounds__(THR, 1) mlp_kernel(
    const float* __restrict__ pt_fea, const int* __restrict__ pt_ind,
    const float* __restrict__ b3, unsigned* __restrict__ out)
{
    extern __shared__ __align__(1024) unsigned char smem[];
    float* sB1 = (float*)(smem + BIAS1);
    float* sB2 = (float*)(smem + BIAS2);
    float* sB3 = (float*)(smem + BIAS3);
    int*   sSeg = (int*)(smem + SEGO);
    const uint32_t sb = smem_u32(smem);
    const uint32_t WB0 = sb + WBUF, WB1 = sb + WBUF + 16384;

    const int tid = threadIdx.x, wid = tid >> 5, lane = tid & 31;
    const int wm = wid & 7, wn = wid >> 3;   // 8 m-groups (32 rows) x 2 n-groups
    const int blk = blockIdx.x;
    const uint32_t aWm = (uint32_t)(wm * 32 * 128);

    // ---- prologue: kick S0, stage biases/segs, L0 compute ----
    stage_async(WB0, g_Wh1, 16384, tid); CP_COMMIT();

    if (tid < 256) {
        int gp = blk * TIL + tid;
        int seg = -1;
        if (gp < P_) {
            int ix = pt_ind[3 * gp], iy = pt_ind[3 * gp + 1], iz = pt_ind[3 * gp + 2];
            int bb = (gp >= N_) ? 1 : 0;
            seg = ((bb * G_ + iz) * G_ + iy) * G_ + ix;
        }
        sSeg[tid] = seg;
    }
    if (tid < 128) sB1[tid] = g_b1f[tid];
    if (tid < 256) sB2[tid] = g_b2f[tid];
    if (tid < 64)  sB3[tid] = b3[tid];

    // L0: 3 -> 64 scalar fp32, fp16 into slot 0 (256 points, 2 threads/pt)
    {
        int p = tid >> 1, j0 = (tid & 1) * 32;
        int gp = blk * TIL + p;
        float x0 = 0.f, x1 = 0.f, x2 = 0.f;
        if (gp < P_) { x0 = pt_fea[gp*3]; x1 = pt_fea[gp*3+1]; x2 = pt_fea[gp*3+2]; }
        #pragma unroll
        for (int j = 0; j < 32; j += 2) {
            int k = j0 + j;
            float v0 = g_b0f[k]   + x0*g_W0f[k]   + x1*g_W0f[64+k]   + x2*g_W0f[128+k];
            float v1 = g_b0f[k+1] + x0*g_W0f[k+1] + x1*g_W0f[64+k+1] + x2*g_W0f[128+k+1];
            v0 = fmaxf(v0, 0.f); v1 = fmaxf(v1, 0.f);
            uint32_t off = sw128((uint32_t)(p * 128 + k * 2));
            *(uint32_t*)(smem + SLOT(0) + off) = pack2h(v0, v1);
        }
    }
    CP_WAIT0();
    __syncthreads();

    // ---- p0: L1 (64->128), in slot0, out slots 1,2; prefetch S1 ----
    stage_async(WB1, g_Wh2, 16384, tid); CP_COMMIT();
    {
        float acc[2][8][4];
        #pragma unroll
        for (int a = 0; a < 2; a++)
            #pragma unroll
            for (int b = 0; b < 8; b++)
                #pragma unroll
                for (int c = 0; c < 4; c++) acc[a][b][c] = 0.f;
        uint32_t bOff = (uint32_t)(wn * 64 * 128);
        mma_kchunk1<8>(acc, sb + SLOT(0) + aWm, WB0 + bOff, lane);
        epi_hidden<8>(acc, smem, SLOT(1 + wn), sB1, wn * 64, wm, lane);
    }
    CP_WAIT0(); __syncthreads();

    // ---- L2 (128->256): g0 over p1,p2 ; g1 over p3,p4 ----
    const int outSlot[4] = {3, 4, 5, 0};
    {
        float acc[2][8][4];
        uint32_t bOff = (uint32_t)(wn * 64 * 128);

        // p1: g0 kc0 on WB1(S1); prefetch S2 -> WB0
        stage_async(WB0, g_Wh2 + 16384, 16384, tid); CP_COMMIT();
        #pragma unroll
        for (int a = 0; a < 2; a++)
            #pragma unroll
            for (int b = 0; b < 8; b++)
                #pragma unroll
                for (int c = 0; c < 4; c++) acc[a][b][c] = 0.f;
        mma_kchunk1<8>(acc, sb + SLOT(1) + aWm, WB1 + bOff, lane);
        CP_WAIT0(); __syncthreads();

        // p2: g0 kc1 on WB0(S2); prefetch S3 -> WB1
        stage_async(WB1, g_Wh2 + 32768, 16384, tid); CP_COMMIT();
        mma_kchunk1<8>(acc, sb + SLOT(2) + aWm, WB0 + bOff, lane);
        epi_hidden<8>(acc, smem, SLOT(outSlot[wn]), sB2, wn * 64, wm, lane);
        CP_WAIT0(); __syncthreads();

        // p3: g1 kc0 on WB1(S3); prefetch S4 -> WB0
        stage_async(WB0, g_Wh2 + 49152, 16384, tid); CP_COMMIT();
        #pragma unroll
        for (int a = 0; a < 2; a++)
            #pragma unroll
            for (int b = 0; b < 8; b++)
                #pragma unroll
                for (int c = 0; c < 4; c++) acc[a][b][c] = 0.f;
        mma_kchunk1<8>(acc, sb + SLOT(1) + aWm, WB1 + bOff, lane);
        CP_WAIT0(); __syncthreads();

        // p4: g1 kc1 on WB0(S4); prefetch S5 (L3 kc0, 8KB) -> WB1
        stage_async(WB1, g_Wh3, 8192, tid); CP_COMMIT();
        mma_kchunk1<8>(acc, sb + SLOT(2) + aWm, WB0 + bOff, lane);
        epi_hidden<8>(acc, smem, SLOT(outSlot[2 + wn]), sB2, 128 + wn * 64, wm, lane);
        CP_WAIT0(); __syncthreads();
    }

    // ---- L3 (256->64) over p5..p8, then scatter ----
    {
        float acc[2][4][4];
        #pragma unroll
        for (int a = 0; a < 2; a++)
            #pragma unroll
            for (int b = 0; b < 4; b++)
                #pragma unroll
                for (int c = 0; c < 4; c++) acc[a][b][c] = 0.f;
        uint32_t bOff = (uint32_t)(wn * 32 * 128);

        // p5: kc0 on WB1(S5); prefetch S6 -> WB0
        stage_async(WB0, g_Wh3 + 8192, 8192, tid); CP_COMMIT();
        mma_kchunk1<4>(acc, sb + SLOT(3) + aWm, WB1 + bOff, lane);
        CP_WAIT0(); __syncthreads();

        // p6: kc1 on WB0(S6); prefetch S7 -> WB1
        stage_async(WB1, g_Wh3 + 16384, 8192, tid); CP_COMMIT();
        mma_kchunk1<4>(acc, sb + SLOT(4) + aWm, WB0 + bOff, lane);
        CP_WAIT0(); __syncthreads();

        // p7: kc2 on WB1(S7); prefetch S8 -> WB0
        stage_async(WB0, g_Wh3 + 24576, 8192, tid); CP_COMMIT();
        mma_kchunk1<4>(acc, sb + SLOT(5) + aWm, WB1 + bOff, lane);
        CP_WAIT0(); __syncthreads();

        // p8: kc3 on WB0(S8)
        mma_kchunk1<4>(acc, sb + SLOT(0) + aWm, WB0 + bOff, lane);

        // scatter-max (branchless encode)
        const int r0 = lane >> 2;
        #pragma unroll
        for (int mt = 0; mt < 2; mt++) {
            int row1 = wm * 32 + mt * 16 + r0;
            int row2 = row1 + 8;
            int seg1 = sSeg[row1], seg2 = sSeg[row2];
            #pragma unroll
            for (int nt = 0; nt < 4; nt++) {
                int col = wn * 32 + nt * 8 + (lane & 3) * 2;
                float bi0 = sB3[col], bi1 = sB3[col + 1];
                if (seg1 >= 0) {
                    unsigned b0a = (unsigned)seg1 * 64u + (unsigned)col;
                    atomicMax(out + b0a,     encf(acc[mt][nt][0] + bi0));
                    atomicMax(out + b0a + 1, encf(acc[mt][nt][1] + bi1));
                }
                if (seg2 >= 0) {
                    unsigned b0a = (unsigned)seg2 * 64u + (unsigned)col;
                    atomicMax(out + b0a,     encf(acc[mt][nt][2] + bi0));
                    atomicMax(out + b0a + 1, encf(acc[mt][nt][3] + bi1));
                }
            }
        }
    }
}

// ---------------- launcher ---------------------------------------------------
extern "C" void kernel_launch(void* const* d_in, const int* in_sizes, int n_in,
                              void* d_out, int out_size)
{
    const float* pt_fea = (const float*)d_in[0];
    const int*   pt_ind = (const int*)  d_in[1];
    const float *bn0g = (const float*)d_in[2],  *bn0b = (const float*)d_in[3],
                *bn0m = (const float*)d_in[4],  *bn0v = (const float*)d_in[5];
    const float *bn1g = (const float*)d_in[6],  *bn1b = (const float*)d_in[7],
                *bn1m = (const float*)d_in[8],  *bn1v = (const float*)d_in[9];
    const float *bn2g = (const float*)d_in[10], *bn2b = (const float*)d_in[11],
                *bn2m = (const float*)d_in[12], *bn2v = (const float*)d_in[13];
    const float *bn3g = (const float*)d_in[14], *bn3b = (const float*)d_in[15],
                *bn3m = (const float*)d_in[16], *bn3v = (const float*)d_in[17];
    const float *W0 = (const float*)d_in[18], *b0 = (const float*)d_in[19];
    const float *W1 = (const float*)d_in[20], *b1 = (const float*)d_in[21];
    const float *W2 = (const float*)d_in[22], *b2 = (const float*)d_in[23];
    const float *W3 = (const float*)d_in[24], *b3 = (const float*)d_in[25];

    cudaFuncSetAttribute(mlp_kernel, cudaFuncAttributeMaxDynamicSharedMemorySize,
                         SMEM_TOTAL);

    const int n4 = NS_ * OUT_ / 4;
    init_fold_kernel<<<(n4 + 255) / 256, 256>>>(
        (uint4*)d_out, n4,
        bn0g, bn0b, bn0m, bn0v, bn1g, bn1b, bn1m, bn1v,
        bn2g, bn2b, bn2m, bn2v, bn3g, bn3b, bn3m, bn3v,
        W0, b0, W1, b1, W2, b2, W3);

    mlp_kernel<<<NT_CTA, THR, SMEM_TOTAL>>>(pt_fea, pt_ind, b3, (unsigned*)d_out);

    decode_kernel<<<(n4 + 255) / 256, 256>>>((uint4*)d_out, n4);
}